// round 1
// baseline (speedup 1.0000x reference)
#include <cuda_runtime.h>

#define TOK   200704       // 64*56*56 tokens
#define CIN   256
#define QKVD  768
#define NHEAD 8
#define HD    32
#define WS    7
#define WT    49           // tokens per window
#define NWIN  4096         // 64 * 8 * 8
#define SCALE 5.656854249f // sqrt(32) -- reference MULTIPLIES by sqrt(hd)

// Scratch (static device globals; allocation inside kernel_launch is forbidden)
__device__ float g_qkv[(size_t)TOK * QKVD];  // [token, 3*nh*hd]
__device__ float g_att[(size_t)TOK * CIN];   // [token, nh*hd] attention output

// ---------------------------------------------------------------------------
// Tiled SGEMM with bias: C[M,N] = A[M,K] @ B[K,N] + bias[N]
// BM=128, BN=64, BK=16, 256 threads, 8x4 micro-tile per thread.
// Assumes M%128==0, N%64==0, K%16==0 (true for all three shapes here).
// ---------------------------------------------------------------------------
__global__ __launch_bounds__(256) void sgemm_bias(
    int M, int N, int K,
    const float* __restrict__ A,
    const float* __restrict__ B,
    const float* __restrict__ bias,
    float* __restrict__ C)
{
    const int BM = 128, BN = 64, BK = 16;
    __shared__ float As[16][128];   // transposed: As[k][m]
    __shared__ float Bs[16][64];

    const int tid = threadIdx.x;
    const int bm = blockIdx.y * BM;
    const int bn = blockIdx.x * BN;

    const int ar = tid >> 2;          // 0..63  (A tile row, two rows per thread)
    const int aq = tid & 3;           // 0..3   (which float4 in the 16-wide k slab)
    const int br = tid >> 4;          // 0..15  (B tile row)
    const int bc = (tid & 15) << 2;   // 0..60  (B tile col, float4)
    const int ty = tid >> 4;          // 0..15  -> 8 rows each
    const int tx = tid & 15;          // 0..15  -> 4 cols each

    float acc[8][4];
#pragma unroll
    for (int m = 0; m < 8; m++)
#pragma unroll
        for (int n = 0; n < 4; n++) acc[m][n] = 0.f;

    for (int k0 = 0; k0 < K; k0 += BK) {
        float4 a0 = *(const float4*)(A + (size_t)(bm + ar) * K + k0 + aq * 4);
        float4 a1 = *(const float4*)(A + (size_t)(bm + ar + 64) * K + k0 + aq * 4);
        As[aq * 4 + 0][ar] = a0.x; As[aq * 4 + 1][ar] = a0.y;
        As[aq * 4 + 2][ar] = a0.z; As[aq * 4 + 3][ar] = a0.w;
        As[aq * 4 + 0][ar + 64] = a1.x; As[aq * 4 + 1][ar + 64] = a1.y;
        As[aq * 4 + 2][ar + 64] = a1.z; As[aq * 4 + 3][ar + 64] = a1.w;
        *(float4*)&Bs[br][bc] = *(const float4*)(B + (size_t)(k0 + br) * N + bn + bc);
        __syncthreads();

#pragma unroll
        for (int k = 0; k < BK; k++) {
            float4 av0 = *(const float4*)&As[k][ty * 8];
            float4 av1 = *(const float4*)&As[k][ty * 8 + 4];
            float4 bv  = *(const float4*)&Bs[k][tx * 4];
            float am[8] = {av0.x, av0.y, av0.z, av0.w, av1.x, av1.y, av1.z, av1.w};
            float bb[4] = {bv.x, bv.y, bv.z, bv.w};
#pragma unroll
            for (int m = 0; m < 8; m++)
#pragma unroll
                for (int n = 0; n < 4; n++) acc[m][n] += am[m] * bb[n];
        }
        __syncthreads();
    }

    float4 biv = *(const float4*)(bias + bn + tx * 4);
#pragma unroll
    for (int m = 0; m < 8; m++) {
        float4 o;
        o.x = acc[m][0] + biv.x; o.y = acc[m][1] + biv.y;
        o.z = acc[m][2] + biv.z; o.w = acc[m][3] + biv.w;
        *(float4*)(C + (size_t)(bm + ty * 8 + m) * N + bn + tx * 4) = o;
    }
}

// ---------------------------------------------------------------------------
// Windowed attention: one block per (window, head). 64 threads; threads 0..48
// each own one query row. q-row + accumulators in registers; k/v read as
// broadcast float4 LDS (all row-threads iterate l in lockstep).
// score = (q . k) * sqrt(32) + pos[idx(r)*13 + idx(l)], idx(t) = t/7 + t%7.
// ---------------------------------------------------------------------------
__global__ __launch_bounds__(64) void attn_kernel(
    const float* __restrict__ qkv,
    const float* __restrict__ pos,
    float* __restrict__ att)
{
    __shared__ float sq[WT * HD];
    __shared__ float sk[WT * HD];
    __shared__ float sv[WT * HD];
    __shared__ float ss[WT * WT];
    __shared__ float spos[169];

    const int id   = blockIdx.x;            // ((b*8 + i)*8 + j)*8 + head
    const int head = id & 7;
    const int j    = (id >> 3) & 7;
    const int i    = (id >> 6) & 7;
    const int b    = id >> 9;
    const int tid  = threadIdx.x;
    const int base = b * 3136 + i * 7 * 56 + j * 7;   // token of window origin

    // Load q/k/v head-slices for the 49 window tokens
    for (int idx = tid; idx < WT * HD; idx += 64) {
        const int t = idx >> 5, d = idx & 31;
        const size_t row = (size_t)(base + (t / 7) * 56 + (t % 7)) * QKVD
                         + head * HD + d;
        sq[idx] = qkv[row];
        sk[idx] = qkv[row + 256];
        sv[idx] = qkv[row + 512];
    }
    for (int idx = tid; idx < 169; idx += 64) spos[idx] = pos[idx];
    __syncthreads();

    if (tid < WT) {
        float qr[HD];
#pragma unroll
        for (int d = 0; d < HD; d++) qr[d] = sq[tid * HD + d];

        const int idxr = tid / 7 + tid % 7;
        const float* prow = spos + idxr * 13;
        const float4* sk4 = (const float4*)sk;
        const float4* sv4 = (const float4*)sv;

        float mx = -1e30f;
#pragma unroll 7
        for (int l = 0; l < WT; l++) {
            float a = 0.f;
#pragma unroll
            for (int d4 = 0; d4 < 8; d4++) {
                float4 kv = sk4[l * 8 + d4];
                a += qr[d4 * 4 + 0] * kv.x + qr[d4 * 4 + 1] * kv.y
                   + qr[d4 * 4 + 2] * kv.z + qr[d4 * 4 + 3] * kv.w;
            }
            a = a * SCALE + prow[l / 7 + l % 7];
            ss[tid * WT + l] = a;
            mx = fmaxf(mx, a);
        }

        float sum = 0.f;
#pragma unroll 7
        for (int l = 0; l < WT; l++) {
            float e = __expf(ss[tid * WT + l] - mx);
            ss[tid * WT + l] = e;
            sum += e;
        }
        const float inv = 1.f / sum;

        float acc[HD];
#pragma unroll
        for (int d = 0; d < HD; d++) acc[d] = 0.f;

#pragma unroll 7
        for (int l = 0; l < WT; l++) {
            const float p = ss[tid * WT + l];
#pragma unroll
            for (int d4 = 0; d4 < 8; d4++) {
                float4 vv = sv4[l * 8 + d4];
                acc[d4 * 4 + 0] += p * vv.x; acc[d4 * 4 + 1] += p * vv.y;
                acc[d4 * 4 + 2] += p * vv.z; acc[d4 * 4 + 3] += p * vv.w;
            }
        }

        const size_t orow = (size_t)(base + (tid / 7) * 56 + (tid % 7)) * CIN
                          + head * HD;
#pragma unroll
        for (int d4 = 0; d4 < 8; d4++) {
            float4 o;
            o.x = acc[d4 * 4 + 0] * inv; o.y = acc[d4 * 4 + 1] * inv;
            o.z = acc[d4 * 4 + 2] * inv; o.w = acc[d4 * 4 + 3] * inv;
            *(float4*)(att + orow + d4 * 4) = o;
        }
    }
}

// ---------------------------------------------------------------------------
extern "C" void kernel_launch(void* const* d_in, const int* in_sizes, int n_in,
                              void* d_out, int out_size)
{
    const float* x      = (const float*)d_in[0];
    const float* pos    = (const float*)d_in[1];
    const float* w_qkv  = (const float*)d_in[2];
    const float* b_qkv  = (const float*)d_in[3];
    const float* w_out  = (const float*)d_in[4];
    const float* b_out  = (const float*)d_in[5];
    float* out = (float*)d_out;

    float *qkvp = nullptr, *attp = nullptr;
    cudaGetSymbolAddress((void**)&qkvp, g_qkv);
    cudaGetSymbolAddress((void**)&attp, g_att);

    // 1) qkv = x @ w_qkv + b_qkv        [200704,256] @ [256,768]
    {
        dim3 grid(QKVD / 64, TOK / 128);
        sgemm_bias<<<grid, 256>>>(TOK, QKVD, CIN, x, w_qkv, b_qkv, qkvp);
    }
    // 2) windowed attention -> g_att    4096 windows x 8 heads
    {
        attn_kernel<<<NWIN * NHEAD, 64>>>(qkvp, pos, attp);
    }
    // 3) out = g_att @ w_out + b_out    [200704,256] @ [256,256]
    {
        dim3 grid(CIN / 64, TOK / 128);
        sgemm_bias<<<grid, 256>>>(TOK, CIN, CIN, attp, w_out, b_out, out);
    }
}

// round 14
// speedup vs baseline: 1.3784x; 1.3784x over previous
#include <cuda_runtime.h>
#include <cstdint>

#define TOK   200704       // 64*56*56 tokens
#define CIN   256
#define QKVD  768
#define NHEAD 8
#define HD    32
#define WT    49
#define NWIN  4096
#define SCALE 5.656854249f // sqrt(32) -- reference MULTIPLIES by sqrt(hd)

// ---------------- scratch (static device globals; no allocs allowed) -------
__device__ float g_qkv[(size_t)TOK * QKVD];
__device__ float g_att[(size_t)TOK * CIN];

// ---------------- helpers ---------------------------------------------------
__device__ __forceinline__ float tf32_rn(float a) {
    uint32_t o;
    asm("cvt.rna.tf32.f32 %0, %1;" : "=r"(o) : "f"(a));
    return __uint_as_float(o);
}

__device__ __forceinline__ void mma_tf32(float* c, const uint32_t* a,
                                         const uint32_t* b) {
    asm volatile(
        "mma.sync.aligned.m16n8k8.row.col.f32.tf32.tf32.f32 "
        "{%0,%1,%2,%3}, {%4,%5,%6,%7}, {%8,%9}, {%0,%1,%2,%3};"
        : "+f"(c[0]), "+f"(c[1]), "+f"(c[2]), "+f"(c[3])
        : "r"(a[0]), "r"(a[1]), "r"(a[2]), "r"(a[3]), "r"(b[0]), "r"(b[1]));
}

// ---------------------------------------------------------------------------
// 3xTF32 mma.sync GEMM:  C[M,N] = A[M,K] @ B[K,N] + bias[N]
// BM=128, BN=128, BK=32. 256 threads = 8 warps (4 m x 2 n), warp tile 32x64.
// Both A and B split hi/lo; C = Ah*Bh + Ah*Bl + Al*Bh (near-fp32 accuracy).
// Smem: A hi/lo [128][36] (pad), B hi/lo [32][136] (pad). Conflict-free LDS.
// ---------------------------------------------------------------------------
#define SA_STRIDE 36
#define SB_STRIDE 136
#define SM_AHI 0
#define SM_ALO (128 * SA_STRIDE)
#define SM_BHI (2 * 128 * SA_STRIDE)
#define SM_BLO (2 * 128 * SA_STRIDE + 32 * SB_STRIDE)
#define SMEM_FLOATS (2 * 128 * SA_STRIDE + 2 * 32 * SB_STRIDE)
#define SMEM_BYTES  (SMEM_FLOATS * 4)

__global__ __launch_bounds__(256, 2) void gemm_mma(
    int M, int N, int K,
    const float* __restrict__ A,
    const float* __restrict__ B,
    const float* __restrict__ bias,
    float* __restrict__ C)
{
    extern __shared__ float sm[];
    float* sAhi = sm + SM_AHI;
    float* sAlo = sm + SM_ALO;
    float* sBhi = sm + SM_BHI;
    float* sBlo = sm + SM_BLO;

    const int tid  = threadIdx.x;
    const int lane = tid & 31;
    const int warp = tid >> 5;
    const int wm   = warp & 3;   // 0..3 -> m offset wm*32
    const int wn   = warp >> 2;  // 0..1 -> n offset wn*64
    const int bm   = blockIdx.x * 128;
    const int bn   = blockIdx.y * 128;

    float acc[2][8][4];
#pragma unroll
    for (int mt = 0; mt < 2; mt++)
#pragma unroll
        for (int nt = 0; nt < 8; nt++)
#pragma unroll
            for (int i = 0; i < 4; i++) acc[mt][nt][i] = 0.f;

    const int r  = lane >> 2;   // 0..7
    const int q  = lane & 3;    // 0..3

    for (int c = 0; c < K / 32; c++) {
        const int k0 = c * 32;
        // ---- stage A (128x32), split hi/lo: 4 float4 per thread ----
#pragma unroll
        for (int i = 0; i < 4; i++) {
            const int idx = tid + i * 256;          // 0..1023
            const int row = idx >> 3;               // 0..127
            const int qq  = idx & 7;                // 0..7
            float4 v = *(const float4*)(A + (size_t)(bm + row) * K + k0 + qq * 4);
            float4 hi, lo;
            hi.x = tf32_rn(v.x); lo.x = v.x - hi.x;
            hi.y = tf32_rn(v.y); lo.y = v.y - hi.y;
            hi.z = tf32_rn(v.z); lo.z = v.z - hi.z;
            hi.w = tf32_rn(v.w); lo.w = v.w - hi.w;
            *(float4*)(sAhi + row * SA_STRIDE + qq * 4) = hi;
            *(float4*)(sAlo + row * SA_STRIDE + qq * 4) = lo;
        }
        // ---- stage B (32x128), split hi/lo: 4 float4 per thread ----
#pragma unroll
        for (int i = 0; i < 4; i++) {
            const int idx = tid + i * 256;          // 0..1023
            const int row = idx >> 5;               // 0..31 (k)
            const int c4  = idx & 31;               // 0..31 (n/4)
            float4 v = *(const float4*)(B + (size_t)(k0 + row) * N + bn + c4 * 4);
            float4 hi, lo;
            hi.x = tf32_rn(v.x); lo.x = v.x - hi.x;
            hi.y = tf32_rn(v.y); lo.y = v.y - hi.y;
            hi.z = tf32_rn(v.z); lo.z = v.z - hi.z;
            hi.w = tf32_rn(v.w); lo.w = v.w - hi.w;
            *(float4*)(sBhi + row * SB_STRIDE + c4 * 4) = hi;
            *(float4*)(sBlo + row * SB_STRIDE + c4 * 4) = lo;
        }
        __syncthreads();

        // ---- compute: 4 k8-steps ----
#pragma unroll
        for (int ks = 0; ks < 4; ks++) {
            const int kk = ks * 8;
            // A frags hi/lo: 2 m-tiles x 4 regs
            uint32_t ah[2][4], al[2][4];
            {
                const int arow = wm * 32 + r;
                const int acol = kk + q;
#pragma unroll
                for (int mt = 0; mt < 2; mt++) {
                    const int base = (arow + mt * 16) * SA_STRIDE + acol;
                    ah[mt][0] = __float_as_uint(sAhi[base]);
                    ah[mt][1] = __float_as_uint(sAhi[base + 8 * SA_STRIDE]);
                    ah[mt][2] = __float_as_uint(sAhi[base + 4]);
                    ah[mt][3] = __float_as_uint(sAhi[base + 8 * SA_STRIDE + 4]);
                    al[mt][0] = __float_as_uint(sAlo[base]);
                    al[mt][1] = __float_as_uint(sAlo[base + 8 * SA_STRIDE]);
                    al[mt][2] = __float_as_uint(sAlo[base + 4]);
                    al[mt][3] = __float_as_uint(sAlo[base + 8 * SA_STRIDE + 4]);
                }
            }
            // n-tiles in 2 groups of 4 to bound register pressure
#pragma unroll
            for (int ng = 0; ng < 2; ng++) {
                uint32_t bh[4][2], bl[4][2];
                {
                    const int krow = kk + q;
                    const int ncol = wn * 64 + ng * 32 + r;
#pragma unroll
                    for (int nt = 0; nt < 4; nt++) {
                        const int o0 = krow * SB_STRIDE + ncol + nt * 8;
                        const int o1 = (krow + 4) * SB_STRIDE + ncol + nt * 8;
                        bh[nt][0] = __float_as_uint(sBhi[o0]);
                        bh[nt][1] = __float_as_uint(sBhi[o1]);
                        bl[nt][0] = __float_as_uint(sBlo[o0]);
                        bl[nt][1] = __float_as_uint(sBlo[o1]);
                    }
                }
#pragma unroll
                for (int mt = 0; mt < 2; mt++)
#pragma unroll
                    for (int nt = 0; nt < 4; nt++) {
                        float* a4 = acc[mt][ng * 4 + nt];
                        mma_tf32(a4, ah[mt], bh[nt]);
                        mma_tf32(a4, ah[mt], bl[nt]);
                        mma_tf32(a4, al[mt], bh[nt]);
                    }
            }
        }
        __syncthreads();
    }

    // ---- epilogue: direct global stores with bias ----
#pragma unroll
    for (int mt = 0; mt < 2; mt++) {
        const int row0 = bm + wm * 32 + mt * 16 + r;
#pragma unroll
        for (int nt = 0; nt < 8; nt++) {
            const int col0 = bn + wn * 64 + nt * 8 + q * 2;
            const float2 bv = *(const float2*)(bias + col0);
            float2 o0, o1;
            o0.x = acc[mt][nt][0] + bv.x; o0.y = acc[mt][nt][1] + bv.y;
            o1.x = acc[mt][nt][2] + bv.x; o1.y = acc[mt][nt][3] + bv.y;
            *(float2*)(C + (size_t)row0 * N + col0) = o0;
            *(float2*)(C + (size_t)(row0 + 8) * N + col0) = o1;
        }
    }
}

// ---------------------------------------------------------------------------
// Windowed attention: one block per (window, head). 64 threads; threads 0..48
// each own one query row.
// ---------------------------------------------------------------------------
__global__ __launch_bounds__(64) void attn_kernel(
    const float* __restrict__ qkv,
    const float* __restrict__ pos,
    float* __restrict__ att)
{
    __shared__ float sq[WT * HD];
    __shared__ float sk[WT * HD];
    __shared__ float sv[WT * HD];
    __shared__ float ss[WT * WT];
    __shared__ float spos[169];

    const int id   = blockIdx.x;
    const int head = id & 7;
    const int j    = (id >> 3) & 7;
    const int i    = (id >> 6) & 7;
    const int b    = id >> 9;
    const int tid  = threadIdx.x;
    const int base = b * 3136 + i * 7 * 56 + j * 7;

    for (int idx = tid; idx < WT * HD; idx += 64) {
        const int t = idx >> 5, d = idx & 31;
        const size_t row = (size_t)(base + (t / 7) * 56 + (t % 7)) * QKVD
                         + head * HD + d;
        sq[idx] = qkv[row];
        sk[idx] = qkv[row + 256];
        sv[idx] = qkv[row + 512];
    }
    for (int idx = tid; idx < 169; idx += 64) spos[idx] = pos[idx];
    __syncthreads();

    if (tid < WT) {
        float qr[HD];
#pragma unroll
        for (int d = 0; d < HD; d++) qr[d] = sq[tid * HD + d];

        const int idxr = tid / 7 + tid % 7;
        const float* prow = spos + idxr * 13;
        const float4* sk4 = (const float4*)sk;
        const float4* sv4 = (const float4*)sv;

        float mx = -1e30f;
#pragma unroll 7
        for (int l = 0; l < WT; l++) {
            float a = 0.f;
#pragma unroll
            for (int d4 = 0; d4 < 8; d4++) {
                float4 kv = sk4[l * 8 + d4];
                a += qr[d4 * 4 + 0] * kv.x + qr[d4 * 4 + 1] * kv.y
                   + qr[d4 * 4 + 2] * kv.z + qr[d4 * 4 + 3] * kv.w;
            }
            a = a * SCALE + prow[l / 7 + l % 7];
            ss[tid * WT + l] = a;
            mx = fmaxf(mx, a);
        }

        float sum = 0.f;
#pragma unroll 7
        for (int l = 0; l < WT; l++) {
            float e = __expf(ss[tid * WT + l] - mx);
            ss[tid * WT + l] = e;
            sum += e;
        }
        const float inv = 1.f / sum;

        float acc[HD];
#pragma unroll
        for (int d = 0; d < HD; d++) acc[d] = 0.f;

#pragma unroll 7
        for (int l = 0; l < WT; l++) {
            const float p = ss[tid * WT + l];
#pragma unroll
            for (int d4 = 0; d4 < 8; d4++) {
                float4 vv = sv4[l * 8 + d4];
                acc[d4 * 4 + 0] += p * vv.x; acc[d4 * 4 + 1] += p * vv.y;
                acc[d4 * 4 + 2] += p * vv.z; acc[d4 * 4 + 3] += p * vv.w;
            }
        }

        const size_t orow = (size_t)(base + (tid / 7) * 56 + (tid % 7)) * CIN
                          + head * HD;
#pragma unroll
        for (int d4 = 0; d4 < 8; d4++) {
            float4 o;
            o.x = acc[d4 * 4 + 0] * inv; o.y = acc[d4 * 4 + 1] * inv;
            o.z = acc[d4 * 4 + 2] * inv; o.w = acc[d4 * 4 + 3] * inv;
            *(float4*)(att + orow + d4 * 4) = o;
        }
    }
}

// ---------------------------------------------------------------------------
extern "C" void kernel_launch(void* const* d_in, const int* in_sizes, int n_in,
                              void* d_out, int out_size)
{
    const float* x      = (const float*)d_in[0];
    const float* pos    = (const float*)d_in[1];
    const float* w_qkv  = (const float*)d_in[2];
    const float* b_qkv  = (const float*)d_in[3];
    const float* w_out  = (const float*)d_in[4];
    const float* b_out  = (const float*)d_in[5];
    float* out = (float*)d_out;

    float *qkvp, *attp;
    cudaGetSymbolAddress((void**)&qkvp, g_qkv);
    cudaGetSymbolAddress((void**)&attp, g_att);

    cudaFuncSetAttribute(gemm_mma, cudaFuncAttributeMaxDynamicSharedMemorySize,
                         SMEM_BYTES);

    // 1) qkv = x @ w_qkv + b_qkv     [200704,256]@[256,768]
    {
        dim3 grid(TOK / 128, QKVD / 128);
        gemm_mma<<<grid, 256, SMEM_BYTES>>>(TOK, QKVD, CIN, x, w_qkv, b_qkv, qkvp);
    }
    // 2) windowed attention
    attn_kernel<<<NWIN * NHEAD, 64>>>(qkvp, pos, attp);
    // 3) out = att @ w_out + b_out   [200704,256]@[256,256]
    {
        dim3 grid(TOK / 128, CIN / 128);
        gemm_mma<<<grid, 256, SMEM_BYTES>>>(TOK, CIN, CIN, attp, w_out, b_out, out);
    }
}